// round 15
// baseline (speedup 1.0000x reference)
#include <cuda_runtime.h>
#include <math_constants.h>
#include <cstdint>

#define N_TOK 4096
#define IN_DIM 256
#define HID 256
#define HEADS 8
#define HD 32
#define QBLK 128
#define KBLK 64
#define NITER (N_TOK / KBLK)
#define KVCH 4                 // KV-range split factor
#define NITER_C (NITER / KVCH) // tiles per chunk (16)
#define KSTR 40    // K tile row stride (words); LDS.64 idx 4g+t conflict-free
#define DVS 72     // V double-row stride (words); LDS.64 idx 4t+g conflict-free
#define BSTR 72    // projqk/projv B-tile row stride (conflict-free: 8t+g)
#define BSTR2 73   // final B-tile row stride (breaks transposed-fill conflicts)

// attn SMEM layout (bytes): double-buffered [Ks | Vs] stages; epilogue aliases
#define KBYTES (KBLK * KSTR * 4)          // 10240
#define VBYTES (32 * DVS * 4)             // 9216 (32 double-rows x 72 words)
#define STAGE_BYTES (KBYTES + VBYTES)     // 19456
#define SBUF_BYTES (2 * STAGE_BYTES)      // 38912

// 1/sqrt(256) * log2(e): exp(x*0.0625) == exp2(x*SC2Q)
#define SC2Q (0.0625f * 1.4426950408889634f)

// Scratch (static __device__ arrays — allocation-free per harness rules)
// g_Q: tf32-rounded, SC2Q-pre-scaled Q (row-linear).
// g_K: tf32-rounded K, columns pair-permuted within 8-groups ([0,4,1,5,2,6,3,7]).
// g_V: tf32-rounded V in double-row layout: ((h*512+jg)*4+t)*64 + 2c + s.
// g_pO/g_pL: per-KV-chunk unnormalized partial O (xcat layout) and row sums.
__device__ float g_Q[HEADS * N_TOK * HD];
__device__ float g_K[HEADS * N_TOK * HD];
__device__ float g_V[HEADS * N_TOK * HD];
__device__ float g_xcat[N_TOK * HID];
__device__ float g_pO[KVCH * N_TOK * HID];
__device__ float g_pL[KVCH * HEADS * N_TOK];

// ===========================================================================
__device__ __forceinline__ uint32_t tf32r(float x) {
    uint32_t u;
    asm("cvt.rna.tf32.f32 %0, %1;" : "=r"(u) : "f"(x));
    return u;
}
__device__ __forceinline__ void split2(float v, uint32_t& hi, uint32_t& lo) {
    hi = tf32r(v);
    lo = tf32r(v - __uint_as_float(hi));
}
__device__ __forceinline__ uint32_t smem_u32(const void* p) {
    uint32_t a;
    asm("{ .reg .u64 t; cvta.to.shared.u64 t, %1; cvt.u32.u64 %0, t; }" : "=r"(a) : "l"(p));
    return a;
}
__device__ __forceinline__ void cp16(uint32_t saddr, const void* gaddr) {
    asm volatile("cp.async.cg.shared.global [%0], [%1], 16;"
                 :: "r"(saddr), "l"(gaddr) : "memory");
}
#define CP_COMMIT() asm volatile("cp.async.commit_group;" ::: "memory")
#define CP_WAIT0()  asm volatile("cp.async.wait_group 0;" ::: "memory")

// pair-permutation within an 8-element group: pos 2t <- elem t, 2t+1 <- elem t+4
__device__ __forceinline__ int slotmap(int r) {
    return (r & ~7) | (((r & 3) << 1) | ((r & 7) >> 2));
}

// D += A * B   (m16n8k8, tf32 inputs as .b32, f32 accumulate)
__device__ __forceinline__ void mma8(float* d, const uint32_t* a,
                                     uint32_t b0, uint32_t b1) {
    asm volatile(
        "mma.sync.aligned.m16n8k8.row.col.f32.tf32.tf32.f32 "
        "{%0,%1,%2,%3}, {%4,%5,%6,%7}, {%8,%9}, {%0,%1,%2,%3};"
        : "+f"(d[0]), "+f"(d[1]), "+f"(d[2]), "+f"(d[3])
        : "r"(a[0]), "r"(a[1]), "r"(a[2]), "r"(a[3]), "r"(b0), "r"(b1));
}

// ---------------------------------------------------------------------------
// Q/K projection via tf32 mma.sync. Q: pre-scaled+rounded, row-linear.
// K: rounded, columns pair-permuted within each 8-group (for LDS.64 in attn).
// ---------------------------------------------------------------------------
__global__ __launch_bounds__(256) void projqk_kernel(
    const float* __restrict__ x,
    const float* __restrict__ peQ, const float* __restrict__ peK,
    const float* __restrict__ WQ, const float* __restrict__ WK,
    const float* __restrict__ Qb, const float* __restrict__ Kb,
    float* __restrict__ outQ, float* __restrict__ outK)
{
    __shared__ uint32_t As[128 * 36];
    __shared__ uint32_t Bs[32 * BSTR];

    const float* pe   = blockIdx.z ? peK : peQ;
    const float* W    = blockIdx.z ? WK  : WQ;
    const float* bias = blockIdx.z ? Kb  : Qb;
    float* out        = blockIdx.z ? outK : outQ;
    const float osc   = blockIdx.z ? 1.0f : SC2Q;
    const int isK     = blockIdx.z;

    const int tid = threadIdx.x;
    const int w = tid >> 5, lane = tid & 31;
    const int g = lane >> 2, t = lane & 3;
    const int wm = w >> 1, wn = w & 1;
    const int m0 = blockIdx.x * 128;
    const int n0 = blockIdx.y * 64;

    float acc[2][4][4] = {};

    for (int k0 = 0; k0 < 1024; k0 += 32) {
        __syncthreads();
        #pragma unroll
        for (int i = 0; i < 4; i++) {
            int idx = tid + 256 * i;
            int row = idx >> 3;
            int col = (idx & 7) * 4;
            const float* src = (k0 < IN_DIM)
                ? &x[(size_t)(m0 + row) * IN_DIM + k0 + col]
                : &pe[(size_t)(m0 + row) * 768 + (k0 - IN_DIM) + col];
            float4 v = *reinterpret_cast<const float4*>(src);
            *reinterpret_cast<uint4*>(&As[row * 36 + col]) =
                make_uint4(tf32r(v.x), tf32r(v.y), tf32r(v.z), tf32r(v.w));
        }
        #pragma unroll
        for (int i = 0; i < 2; i++) {
            int idx = tid + 256 * i;
            int kk = idx >> 4;
            int c = (idx & 15) * 4;
            int col = n0 + c;
            float4 v = *reinterpret_cast<const float4*>(
                &W[((size_t)(col >> 5) * 1024 + k0 + kk) * HD + (col & 31)]);
            *reinterpret_cast<uint4*>(&Bs[kk * BSTR + c]) =
                make_uint4(tf32r(v.x), tf32r(v.y), tf32r(v.z), tf32r(v.w));
        }
        __syncthreads();

        #pragma unroll
        for (int ks = 0; ks < 4; ks++) {
            uint32_t af[2][4];
            #pragma unroll
            for (int mt = 0; mt < 2; mt++) {
                int rb = (wm * 32 + mt * 16) * 36 + ks * 8 + t;
                af[mt][0] = As[rb + g * 36];
                af[mt][1] = As[rb + (g + 8) * 36];
                af[mt][2] = As[rb + g * 36 + 4];
                af[mt][3] = As[rb + (g + 8) * 36 + 4];
            }
            #pragma unroll
            for (int nt = 0; nt < 4; nt++) {
                uint32_t b0 = Bs[(ks * 8 + t) * BSTR + wn * 32 + nt * 8 + g];
                uint32_t b1 = Bs[(ks * 8 + t + 4) * BSTR + wn * 32 + nt * 8 + g];
                mma8(acc[0][nt], af[0], b0, b1);
                mma8(acc[1][nt], af[1], b0, b1);
            }
        }
    }

    #pragma unroll
    for (int mt = 0; mt < 2; mt++) {
        int r0 = m0 + wm * 32 + mt * 16 + g;
        #pragma unroll
        for (int nt = 0; nt < 4; nt++) {
            int col = n0 + wn * 32 + nt * 8 + 2 * t;
            int hh = col >> 5, inner = col & 31;
            float bv0 = bias[col], bv1 = bias[col + 1];
            float z0 = __uint_as_float(tf32r((acc[mt][nt][0] + bv0) * osc));
            float z1 = __uint_as_float(tf32r((acc[mt][nt][1] + bv1) * osc));
            float z2 = __uint_as_float(tf32r((acc[mt][nt][2] + bv0) * osc));
            float z3 = __uint_as_float(tf32r((acc[mt][nt][3] + bv1) * osc));
            if (isK) {
                int w0 = slotmap(inner), w1 = slotmap(inner + 1);
                float* o0 = &out[((size_t)hh * N_TOK + r0) * HD];
                float* o1 = &out[((size_t)hh * N_TOK + r0 + 8) * HD];
                o0[w0] = z0; o0[w1] = z1;
                o1[w0] = z2; o1[w1] = z3;
            } else {
                *reinterpret_cast<float2*>(
                    &out[((size_t)hh * N_TOK + r0) * HD + inner]) = make_float2(z0, z1);
                *reinterpret_cast<float2*>(
                    &out[((size_t)hh * N_TOK + r0 + 8) * HD + inner]) = make_float2(z2, z3);
            }
        }
    }
}

// ---------------------------------------------------------------------------
// V projection, split-tf32. Epilogue writes V in the attn double-row layout.
// ---------------------------------------------------------------------------
__global__ __launch_bounds__(256) void projv_tc_kernel(
    const float* __restrict__ x, const float* __restrict__ W,
    const float* __restrict__ bias, float* __restrict__ out)
{
    __shared__ uint32_t Ah[64 * 36], Al[64 * 36];
    __shared__ uint32_t Bh[32 * BSTR], Bl[32 * BSTR];

    const int tid = threadIdx.x;
    const int w = tid >> 5, lane = tid & 31;
    const int g = lane >> 2, t = lane & 3;
    const int wm = w & 1, wn = w >> 1;
    const int m0 = blockIdx.x * 64;
    const int n0 = blockIdx.y * 64;

    float acc[2][2][4] = {};

    for (int k0 = 0; k0 < 256; k0 += 32) {
        __syncthreads();
        #pragma unroll
        for (int i = 0; i < 2; i++) {
            int idx = tid + 256 * i;
            int row = idx >> 3;
            int col = (idx & 7) * 4;
            float4 v = *reinterpret_cast<const float4*>(
                &x[(size_t)(m0 + row) * IN_DIM + k0 + col]);
            uint4 h, l;
            split2(v.x, h.x, l.x); split2(v.y, h.y, l.y);
            split2(v.z, h.z, l.z); split2(v.w, h.w, l.w);
            *reinterpret_cast<uint4*>(&Ah[row * 36 + col]) = h;
            *reinterpret_cast<uint4*>(&Al[row * 36 + col]) = l;
        }
        #pragma unroll
        for (int i = 0; i < 2; i++) {
            int idx = tid + 256 * i;
            int kk = idx >> 4;
            int c = (idx & 15) * 4;
            int col = n0 + c;
            float4 v = *reinterpret_cast<const float4*>(
                &W[((size_t)(col >> 5) * 256 + k0 + kk) * HD + (col & 31)]);
            uint4 h, l;
            split2(v.x, h.x, l.x); split2(v.y, h.y, l.y);
            split2(v.z, h.z, l.z); split2(v.w, h.w, l.w);
            *reinterpret_cast<uint4*>(&Bh[kk * BSTR + c]) = h;
            *reinterpret_cast<uint4*>(&Bl[kk * BSTR + c]) = l;
        }
        __syncthreads();

        #pragma unroll
        for (int ks = 0; ks < 4; ks++) {
            uint32_t afh[2][4], afl[2][4];
            #pragma unroll
            for (int mt = 0; mt < 2; mt++) {
                int rb = (wm * 32 + mt * 16) * 36 + ks * 8 + t;
                afh[mt][0] = Ah[rb + g * 36];
                afh[mt][1] = Ah[rb + (g + 8) * 36];
                afh[mt][2] = Ah[rb + g * 36 + 4];
                afh[mt][3] = Ah[rb + (g + 8) * 36 + 4];
                afl[mt][0] = Al[rb + g * 36];
                afl[mt][1] = Al[rb + (g + 8) * 36];
                afl[mt][2] = Al[rb + g * 36 + 4];
                afl[mt][3] = Al[rb + (g + 8) * 36 + 4];
            }
            #pragma unroll
            for (int nt = 0; nt < 2; nt++) {
                int cb = wn * 16 + nt * 8 + g;
                uint32_t b0h = Bh[(ks * 8 + t) * BSTR + cb];
                uint32_t b1h = Bh[(ks * 8 + t + 4) * BSTR + cb];
                uint32_t b0l = Bl[(ks * 8 + t) * BSTR + cb];
                uint32_t b1l = Bl[(ks * 8 + t + 4) * BSTR + cb];
                #pragma unroll
                for (int mt = 0; mt < 2; mt++) {
                    mma8(acc[mt][nt], afh[mt], b0h, b1h);
                    mma8(acc[mt][nt], afh[mt], b0l, b1l);
                    mma8(acc[mt][nt], afl[mt], b0h, b1h);
                }
            }
        }
    }

    // epilogue: double-row layout. r0 ≡ g (mod 8); tv=g&3, sv=g>>2.
    const int tv = g & 3, sv = g >> 2;
    #pragma unroll
    for (int mt = 0; mt < 2; mt++) {
        int r0 = m0 + wm * 32 + mt * 16 + g;
        int jg0 = r0 >> 3;
        #pragma unroll
        for (int nt = 0; nt < 2; nt++) {
            int col = n0 + wn * 16 + nt * 8 + 2 * t;
            int hh = col >> 5, c = col & 31;
            float bv0 = bias[col], bv1 = bias[col + 1];
            float z0 = __uint_as_float(tf32r(acc[mt][nt][0] + bv0));
            float z1 = __uint_as_float(tf32r(acc[mt][nt][1] + bv1));
            float z2 = __uint_as_float(tf32r(acc[mt][nt][2] + bv0));
            float z3 = __uint_as_float(tf32r(acc[mt][nt][3] + bv1));
            size_t b0i = ((size_t)(hh * 512 + jg0) * 4 + tv) * 64 + sv;
            size_t b1i = ((size_t)(hh * 512 + jg0 + 1) * 4 + tv) * 64 + sv;
            out[b0i + 2 * c] = z0;  out[b0i + 2 * (c + 1)] = z1;
            out[b1i + 2 * c] = z2;  out[b1i + 2 * (c + 1)] = z3;
        }
    }
}

// ---------------------------------------------------------------------------
// Final linear, split-tf32: out = xcat @ lw^T + lb (known-good)
// ---------------------------------------------------------------------------
__global__ __launch_bounds__(256) void final_tc_kernel(
    const float* __restrict__ xcat, const float* __restrict__ lw,
    const float* __restrict__ lb, float* __restrict__ out)
{
    __shared__ uint32_t Ah[64 * 36], Al[64 * 36];
    __shared__ uint32_t Bh[32 * BSTR2], Bl[32 * BSTR2];

    const int tid = threadIdx.x;
    const int w = tid >> 5, lane = tid & 31;
    const int g = lane >> 2, t = lane & 3;
    const int wm = w & 1, wn = w >> 1;
    const int m0 = blockIdx.x * 64;
    const int n0 = blockIdx.y * 64;

    float acc[2][2][4] = {};

    for (int k0 = 0; k0 < 256; k0 += 32) {
        __syncthreads();
        #pragma unroll
        for (int i = 0; i < 2; i++) {
            int idx = tid + 256 * i;
            int row = idx >> 3;
            int col = (idx & 7) * 4;
            float4 v = *reinterpret_cast<const float4*>(
                &xcat[(size_t)(m0 + row) * HID + k0 + col]);
            uint4 h, l;
            split2(v.x, h.x, l.x); split2(v.y, h.y, l.y);
            split2(v.z, h.z, l.z); split2(v.w, h.w, l.w);
            *reinterpret_cast<uint4*>(&Ah[row * 36 + col]) = h;
            *reinterpret_cast<uint4*>(&Al[row * 36 + col]) = l;
        }
        #pragma unroll
        for (int i = 0; i < 2; i++) {
            int idx = tid + 256 * i;
            int c = idx >> 3;
            int kq = (idx & 7) * 4;
            float4 v = *reinterpret_cast<const float4*>(
                &lw[(size_t)(n0 + c) * HID + k0 + kq]);
            uint32_t h0, l0v, h1, l1v, h2, l2v, h3, l3v;
            split2(v.x, h0, l0v); split2(v.y, h1, l1v);
            split2(v.z, h2, l2v); split2(v.w, h3, l3v);
            Bh[(kq + 0) * BSTR2 + c] = h0;  Bl[(kq + 0) * BSTR2 + c] = l0v;
            Bh[(kq + 1) * BSTR2 + c] = h1;  Bl[(kq + 1) * BSTR2 + c] = l1v;
            Bh[(kq + 2) * BSTR2 + c] = h2;  Bl[(kq + 2) * BSTR2 + c] = l2v;
            Bh[(kq + 3) * BSTR2 + c] = h3;  Bl[(kq + 3) * BSTR2 + c] = l3v;
        }
        __syncthreads();

        #pragma unroll
        for (int ks = 0; ks < 4; ks++) {
            uint32_t afh[2][4], afl[2][4];
            #pragma unroll
            for (int mt = 0; mt < 2; mt++) {
                int rb = (wm * 32 + mt * 16) * 36 + ks * 8 + t;
                afh[mt][0] = Ah[rb + g * 36];
                afh[mt][1] = Ah[rb + (g + 8) * 36];
                afh[mt][2] = Ah[rb + g * 36 + 4];
                afh[mt][3] = Ah[rb + (g + 8) * 36 + 4];
                afl[mt][0] = Al[rb + g * 36];
                afl[mt][1] = Al[rb + (g + 8) * 36];
                afl[mt][2] = Al[rb + g * 36 + 4];
                afl[mt][3] = Al[rb + (g + 8) * 36 + 4];
            }
            #pragma unroll
            for (int nt = 0; nt < 2; nt++) {
                int cb = wn * 16 + nt * 8 + g;
                uint32_t b0h = Bh[(ks * 8 + t) * BSTR2 + cb];
                uint32_t b1h = Bh[(ks * 8 + t + 4) * BSTR2 + cb];
                uint32_t b0l = Bl[(ks * 8 + t) * BSTR2 + cb];
                uint32_t b1l = Bl[(ks * 8 + t + 4) * BSTR2 + cb];
                #pragma unroll
                for (int mt = 0; mt < 2; mt++) {
                    mma8(acc[mt][nt], afh[mt], b0h, b1h);
                    mma8(acc[mt][nt], afh[mt], b0l, b1l);
                    mma8(acc[mt][nt], afl[mt], b0h, b1h);
                }
            }
        }
    }

    #pragma unroll
    for (int mt = 0; mt < 2; mt++) {
        int r0 = m0 + wm * 32 + mt * 16 + g;
        #pragma unroll
        for (int nt = 0; nt < 2; nt++) {
            int col = n0 + wn * 16 + nt * 8 + 2 * t;
            float bv0 = lb[col], bv1 = lb[col + 1];
            *reinterpret_cast<float2*>(&out[(size_t)r0 * HID + col]) =
                make_float2(acc[mt][nt][0] + bv0, acc[mt][nt][1] + bv1);
            *reinterpret_cast<float2*>(&out[(size_t)(r0 + 8) * HID + col]) =
                make_float2(acc[mt][nt][2] + bv0, acc[mt][nt][3] + bv1);
        }
    }
}

// ---------------------------------------------------------------------------
// Flash attention, KV-split: grid (N/128, HEADS, KVCH); each CTA handles
// NITER_C KV tiles and writes UNNORMALIZED partial O + row sums to scratch.
// (No max-subtraction -> partials merge by simple addition.)
// ---------------------------------------------------------------------------
__global__ __launch_bounds__(256) void attn_mma_kernel(
    const float* __restrict__ Qg, const float* __restrict__ Kg,
    const float* __restrict__ Vg, float* __restrict__ pO,
    float* __restrict__ pL)
{
    __shared__ __align__(16) char sbuf[SBUF_BYTES];
    const uint32_t sb = smem_u32(sbuf);

    const int tid = threadIdx.x;
    const int w = tid >> 5;
    const int lane = tid & 31;
    const int g = lane >> 2;
    const int t = lane & 3;
    const int h = blockIdx.y;
    const int z = blockIdx.z;
    const int q0 = blockIdx.x * QBLK;
    const int wm = w >> 1;
    const int m0 = wm * 32;
    const int c0 = (w & 1) * 32;      // KV col half
    const int jb = (c0 >> 3);         // base 8-row group of this warp's half
    const int kb0 = z * NITER_C;

    const float* Qh = Qg + (size_t)h * N_TOK * HD;
    const float* Kh = Kg + (size_t)h * N_TOK * HD;
    const float* Vh = Vg + (size_t)h * N_TOK * HD;

    // ---- Q fragments (pre-scaled + pre-rounded bits, direct load) ----
    uint32_t qf[2][4][4];
    #pragma unroll
    for (int mt = 0; mt < 2; mt++) {
        const float* qr0 = Qh + (size_t)(q0 + m0 + mt * 16 + g) * HD;
        const float* qr1 = qr0 + 8 * HD;
        #pragma unroll
        for (int s = 0; s < 4; s++) {
            qf[mt][s][0] = __float_as_uint(qr0[8 * s + t]);
            qf[mt][s][1] = __float_as_uint(qr1[8 * s + t]);
            qf[mt][s][2] = __float_as_uint(qr0[8 * s + t + 4]);
            qf[mt][s][3] = __float_as_uint(qr1[8 * s + t + 4]);
        }
    }

    float of[2][4][4] = {};
    float l[2][2] = {};

    // ---- fill geometry ----
    const int frow = tid >> 3;            // 0..31 (K rows frow, frow+32)
    const int fb = (tid & 7) * 16;        // byte offset within 128B K row
    const int ks0 = slotmap(frow);
    const int ks1 = slotmap(frow + 32);
    const int vq0 = tid, vq1 = tid + 256;

    #define K_FILL(kb_, base_) do { \
        const char* kg_ = (const char*)(Kh + (size_t)((kb_) * KBLK + frow) * HD) + fb; \
        cp16((base_) + ks0 * (KSTR * 4) + fb, kg_); \
        cp16((base_) + ks1 * (KSTR * 4) + fb, kg_ + 32 * HD * 4); \
    } while (0)
    #define V_FILL(kb_, base_) do { \
        int q_ = vq0; \
        const float* vs_ = Vh + ((size_t)(8 * (kb_) + (q_ >> 6)) * 4 + ((q_ >> 4) & 3)) * 64 + (q_ & 15) * 4; \
        cp16((base_) + KBYTES + (q_ >> 4) * (DVS * 4) + (q_ & 15) * 16, vs_); \
        q_ = vq1; \
        vs_ = Vh + ((size_t)(8 * (kb_) + (q_ >> 6)) * 4 + ((q_ >> 4) & 3)) * 64 + (q_ & 15) * 4; \
        cp16((base_) + KBYTES + (q_ >> 4) * (DVS * 4) + (q_ & 15) * 16, vs_); \
    } while (0)

    // preload first tile of this chunk into stage 0
    K_FILL(kb0, sb);
    V_FILL(kb0, sb);
    CP_COMMIT();

    for (int it = 0; it < NITER_C; it++) {
        const int kb = kb0 + it;
        CP_WAIT0();
        __syncthreads();

        const int stage = it & 1;
        if (it + 1 < NITER_C) {
            const uint32_t nb = sb + (stage ^ 1) * STAGE_BYTES;
            K_FILL(kb + 1, nb);
            V_FILL(kb + 1, nb);
            CP_COMMIT();
        }

        const uint32_t* Ksp = reinterpret_cast<const uint32_t*>(sbuf + stage * STAGE_BYTES);
        const uint32_t* Vsp = reinterpret_cast<const uint32_t*>(sbuf + stage * STAGE_BYTES + KBYTES);

        #pragma unroll
        for (int j = 0; j < 4; j++) {
            const uint32_t* kbp = &Ksp[(c0 + 8 * j + g) * KSTR + 2 * t];
            uint2 kp0 = *reinterpret_cast<const uint2*>(kbp);
            uint2 kp1 = *reinterpret_cast<const uint2*>(kbp + 8);
            uint2 kp2 = *reinterpret_cast<const uint2*>(kbp + 16);
            uint2 kp3 = *reinterpret_cast<const uint2*>(kbp + 24);

            float sf[2][4] = {};
            #pragma unroll
            for (int mt = 0; mt < 2; mt++) {
                mma8(sf[mt], qf[mt][0], kp0.x, kp0.y);
                mma8(sf[mt], qf[mt][1], kp1.x, kp1.y);
                mma8(sf[mt], qf[mt][2], kp2.x, kp2.y);
                mma8(sf[mt], qf[mt][3], kp3.x, kp3.y);
            }

            const uint32_t* vbp = &Vsp[((jb + j) * 4 + t) * DVS + 2 * g];
            uint2 v0 = *reinterpret_cast<const uint2*>(vbp);
            uint2 v1 = *reinterpret_cast<const uint2*>(vbp + 16);
            uint2 v2 = *reinterpret_cast<const uint2*>(vbp + 32);
            uint2 v3 = *reinterpret_cast<const uint2*>(vbp + 48);

            #pragma unroll
            for (int mt = 0; mt < 2; mt++) {
                float e0 = exp2f(sf[mt][0]);
                float e1 = exp2f(sf[mt][1]);
                float e2 = exp2f(sf[mt][2]);
                float e3 = exp2f(sf[mt][3]);
                l[mt][0] += e0 + e1;
                l[mt][1] += e2 + e3;

                uint32_t pa[4];
                pa[0] = __float_as_uint(e0);
                pa[1] = __float_as_uint(e2);
                pa[2] = __float_as_uint(e1);
                pa[3] = __float_as_uint(e3);

                mma8(of[mt][0], pa, v0.x, v0.y);
                mma8(of[mt][1], pa, v1.x, v1.y);
                mma8(of[mt][2], pa, v2.x, v2.y);
                mma8(of[mt][3], pa, v3.x, v3.y);
            }
        }
    }

    // ---- epilogue: pair-combine, write UNNORMALIZED partials ----
    __syncthreads();
    float* sO = reinterpret_cast<float*>(sbuf);
    float* sL = reinterpret_cast<float*>(sbuf + QBLK * 34 * 4);

    #pragma unroll
    for (int mt = 0; mt < 2; mt++) {
        l[mt][0] += __shfl_xor_sync(0xffffffffu, l[mt][0], 1);
        l[mt][0] += __shfl_xor_sync(0xffffffffu, l[mt][0], 2);
        l[mt][1] += __shfl_xor_sync(0xffffffffu, l[mt][1], 1);
        l[mt][1] += __shfl_xor_sync(0xffffffffu, l[mt][1], 2);
    }

    if (w & 1) {
        #pragma unroll
        for (int mt = 0; mt < 2; mt++) {
            int r = m0 + mt * 16 + g;
            if (t == 0) { sL[r] = l[mt][0]; sL[r + 8] = l[mt][1]; }
            #pragma unroll
            for (int nn = 0; nn < 4; nn++) {
                *reinterpret_cast<float2*>(&sO[r * 34 + 8 * nn + 2 * t]) =
                    make_float2(of[mt][nn][0], of[mt][nn][1]);
                *reinterpret_cast<float2*>(&sO[(r + 8) * 34 + 8 * nn + 2 * t]) =
                    make_float2(of[mt][nn][2], of[mt][nn][3]);
            }
        }
    }
    __syncthreads();
    if (!(w & 1)) {
        #pragma unroll
        for (int mt = 0; mt < 2; mt++) {
            int r = m0 + mt * 16 + g;
            float L0 = l[mt][0] + sL[r];
            float L1 = l[mt][1] + sL[r + 8];
            if (t == 0) {
                pL[((size_t)z * HEADS + h) * N_TOK + q0 + r] = L0;
                pL[((size_t)z * HEADS + h) * N_TOK + q0 + r + 8] = L1;
            }
            #pragma unroll
            for (int nn = 0; nn < 4; nn++) {
                float2 a = *reinterpret_cast<const float2*>(&sO[r * 34 + 8 * nn + 2 * t]);
                float2 b = *reinterpret_cast<const float2*>(&sO[(r + 8) * 34 + 8 * nn + 2 * t]);
                *reinterpret_cast<float2*>(
                    &pO[((size_t)z * N_TOK + q0 + r) * HID + h * HD + 8 * nn + 2 * t]) =
                    make_float2(of[mt][nn][0] + a.x, of[mt][nn][1] + a.y);
                *reinterpret_cast<float2*>(
                    &pO[((size_t)z * N_TOK + q0 + r + 8) * HID + h * HD + 8 * nn + 2 * t]) =
                    make_float2(of[mt][nn][2] + b.x, of[mt][nn][3] + b.y);
            }
        }
    }
}

// ---------------------------------------------------------------------------
// Merge: xcat = (sum_z pO_z) / (sum_z pL_z).  1M elems, L2-resident, ~2us.
// ---------------------------------------------------------------------------
__global__ __launch_bounds__(256) void merge_kernel(
    const float* __restrict__ pO, const float* __restrict__ pL,
    float* __restrict__ xcat)
{
    int idx = blockIdx.x * 256 + threadIdx.x;   // 0 .. 4096*64-1
    int row = idx >> 6;
    int c4 = (idx & 63) * 4;
    int h = c4 >> 5;

    float4 s = make_float4(0.f, 0.f, 0.f, 0.f);
    float L = 0.f;
    #pragma unroll
    for (int z = 0; z < KVCH; z++) {
        float4 v = *reinterpret_cast<const float4*>(
            &pO[((size_t)z * N_TOK + row) * HID + c4]);
        s.x += v.x; s.y += v.y; s.z += v.z; s.w += v.w;
        L += pL[((size_t)z * HEADS + h) * N_TOK + row];
    }
    float inv = 1.0f / L;
    *reinterpret_cast<float4*>(&xcat[(size_t)row * HID + c4]) =
        make_float4(s.x * inv, s.y * inv, s.z * inv, s.w * inv);
}

// ---------------------------------------------------------------------------
extern "C" void kernel_launch(void* const* d_in, const int* in_sizes, int n_in,
                              void* d_out, int out_size)
{
    const float* x   = (const float*)d_in[0];
    const float* peQ = (const float*)d_in[1];
    const float* peK = (const float*)d_in[2];
    const float* WQ  = (const float*)d_in[4];
    const float* WK  = (const float*)d_in[5];
    const float* WV  = (const float*)d_in[6];
    const float* Qb  = (const float*)d_in[7];
    const float* Kb  = (const float*)d_in[8];
    const float* Vb  = (const float*)d_in[9];
    const float* lw  = (const float*)d_in[10];
    const float* lb  = (const float*)d_in[11];
    float* out = (float*)d_out;

    float *qp, *kp, *vp, *xc, *po, *pl;
    cudaGetSymbolAddress((void**)&qp, g_Q);
    cudaGetSymbolAddress((void**)&kp, g_K);
    cudaGetSymbolAddress((void**)&vp, g_V);
    cudaGetSymbolAddress((void**)&xc, g_xcat);
    cudaGetSymbolAddress((void**)&po, g_pO);
    cudaGetSymbolAddress((void**)&pl, g_pL);

    projqk_kernel<<<dim3(N_TOK / 128, HID / 64, 2), 256>>>(
        x, peQ, peK, WQ, WK, Qb, Kb, qp, kp);
    projv_tc_kernel<<<dim3(N_TOK / 64, HID / 64), 256>>>(x, WV, Vb, vp);
    attn_mma_kernel<<<dim3(N_TOK / QBLK, HEADS, KVCH), 256>>>(qp, kp, vp, po, pl);
    merge_kernel<<<(N_TOK * HID / 4) / 256, 256>>>(po, pl, xc);
    final_tc_kernel<<<dim3(N_TOK / 64, HID / 64), 256>>>(xc, lw, lb, out);
}

// round 16
// speedup vs baseline: 1.4327x; 1.4327x over previous
#include <cuda_runtime.h>
#include <cuda_fp16.h>
#include <math_constants.h>
#include <cstdint>

#define N_TOK 4096
#define IN_DIM 256
#define HID 256
#define HEADS 8
#define HD 32
#define QBLK 128
#define KBLK 64
#define NITER (N_TOK / KBLK)
#define KW 20      // K smem row stride (32b words); banks 20g+t conflict-free
#define VWS 12     // V smem (q,d)-row stride (words); banks 12g+t conflict-free
#define BSTR 72    // projqk/projv B-tile row stride (conflict-free: 8t+g)
#define BSTR2 73   // final B-tile row stride

// attn SMEM: double-buffered [K | V] stages (fp16); epilogue aliases
#define KBYTES (64 * KW * 4)              // 5120
#define VBYTES (4 * 32 * VWS * 4)         // 6144
#define STAGE_BYTES (KBYTES + VBYTES)     // 11264
#define SBUF_BYTES (2 * STAGE_BYTES)      // 22528

// 1/sqrt(256) * log2(e): exp(x*0.0625) == exp2(x*SC2Q)
#define SC2Q (0.0625f * 1.4426950408889634f)

// Scratch (static __device__ arrays — allocation-free per harness rules)
// g_Qh: fp16, SC2Q-pre-scaled Q, row-major [h][n][d].
// g_Kh: fp16 K, row-major [h][n][d].
// g_Vh: fp16 V in row-pair layout: ((h*256+jg2)*32 + d)*16 + (r mod 16),
//       jg2 = r/16 (16-row groups); half2 word w holds rows {2w, 2w+1}.
__device__ __half g_Qh[HEADS * N_TOK * HD];
__device__ __half g_Kh[HEADS * N_TOK * HD];
__device__ __half g_Vh[HEADS * N_TOK * HD];
__device__ float g_xcat[N_TOK * HID];

// ===========================================================================
__device__ __forceinline__ uint32_t tf32r(float x) {
    uint32_t u;
    asm("cvt.rna.tf32.f32 %0, %1;" : "=r"(u) : "f"(x));
    return u;
}
__device__ __forceinline__ void split2(float v, uint32_t& hi, uint32_t& lo) {
    hi = tf32r(v);
    lo = tf32r(v - __uint_as_float(hi));
}
__device__ __forceinline__ uint32_t smem_u32(const void* p) {
    uint32_t a;
    asm("{ .reg .u64 t; cvta.to.shared.u64 t, %1; cvt.u32.u64 %0, t; }" : "=r"(a) : "l"(p));
    return a;
}
__device__ __forceinline__ void cp16(uint32_t saddr, const void* gaddr) {
    asm volatile("cp.async.cg.shared.global [%0], [%1], 16;"
                 :: "r"(saddr), "l"(gaddr) : "memory");
}
#define CP_COMMIT() asm volatile("cp.async.commit_group;" ::: "memory")
#define CP_WAIT0()  asm volatile("cp.async.wait_group 0;" ::: "memory")

// pack (lo, hi) floats -> f16x2 (lo in low half)
__device__ __forceinline__ uint32_t h2pack(float lo, float hi) {
    uint32_t r;
    asm("cvt.rn.f16x2.f32 %0, %1, %2;" : "=r"(r) : "f"(hi), "f"(lo));
    return r;
}

// tf32 m16n8k8: D += A*B
__device__ __forceinline__ void mma8(float* d, const uint32_t* a,
                                     uint32_t b0, uint32_t b1) {
    asm volatile(
        "mma.sync.aligned.m16n8k8.row.col.f32.tf32.tf32.f32 "
        "{%0,%1,%2,%3}, {%4,%5,%6,%7}, {%8,%9}, {%0,%1,%2,%3};"
        : "+f"(d[0]), "+f"(d[1]), "+f"(d[2]), "+f"(d[3])
        : "r"(a[0]), "r"(a[1]), "r"(a[2]), "r"(a[3]), "r"(b0), "r"(b1));
}
// fp16 m16n8k16: D += A*B (fp32 accumulate) — 2x MAC/instr vs tf32 k8
__device__ __forceinline__ void mma16h(float* d, const uint32_t* a,
                                       uint32_t b0, uint32_t b1) {
    asm volatile(
        "mma.sync.aligned.m16n8k16.row.col.f32.f16.f16.f32 "
        "{%0,%1,%2,%3}, {%4,%5,%6,%7}, {%8,%9}, {%0,%1,%2,%3};"
        : "+f"(d[0]), "+f"(d[1]), "+f"(d[2]), "+f"(d[3])
        : "r"(a[0]), "r"(a[1]), "r"(a[2]), "r"(a[3]), "r"(b0), "r"(b1));
}

// ---------------------------------------------------------------------------
// Q/K projection via tf32 mma.sync; epilogue emits fp16 (Q pre-scaled SC2Q).
// ---------------------------------------------------------------------------
__global__ __launch_bounds__(256) void projqk_kernel(
    const float* __restrict__ x,
    const float* __restrict__ peQ, const float* __restrict__ peK,
    const float* __restrict__ WQ, const float* __restrict__ WK,
    const float* __restrict__ Qb, const float* __restrict__ Kb,
    __half* __restrict__ outQ, __half* __restrict__ outK)
{
    __shared__ uint32_t As[128 * 36];
    __shared__ uint32_t Bs[32 * BSTR];

    const float* pe   = blockIdx.z ? peK : peQ;
    const float* W    = blockIdx.z ? WK  : WQ;
    const float* bias = blockIdx.z ? Kb  : Qb;
    __half* out       = blockIdx.z ? outK : outQ;
    const float osc   = blockIdx.z ? 1.0f : SC2Q;

    const int tid = threadIdx.x;
    const int w = tid >> 5, lane = tid & 31;
    const int g = lane >> 2, t = lane & 3;
    const int wm = w >> 1, wn = w & 1;
    const int m0 = blockIdx.x * 128;
    const int n0 = blockIdx.y * 64;

    float acc[2][4][4] = {};

    for (int k0 = 0; k0 < 1024; k0 += 32) {
        __syncthreads();
        #pragma unroll
        for (int i = 0; i < 4; i++) {
            int idx = tid + 256 * i;
            int row = idx >> 3;
            int col = (idx & 7) * 4;
            const float* src = (k0 < IN_DIM)
                ? &x[(size_t)(m0 + row) * IN_DIM + k0 + col]
                : &pe[(size_t)(m0 + row) * 768 + (k0 - IN_DIM) + col];
            float4 v = *reinterpret_cast<const float4*>(src);
            *reinterpret_cast<uint4*>(&As[row * 36 + col]) =
                make_uint4(tf32r(v.x), tf32r(v.y), tf32r(v.z), tf32r(v.w));
        }
        #pragma unroll
        for (int i = 0; i < 2; i++) {
            int idx = tid + 256 * i;
            int kk = idx >> 4;
            int c = (idx & 15) * 4;
            int col = n0 + c;
            float4 v = *reinterpret_cast<const float4*>(
                &W[((size_t)(col >> 5) * 1024 + k0 + kk) * HD + (col & 31)]);
            *reinterpret_cast<uint4*>(&Bs[kk * BSTR + c]) =
                make_uint4(tf32r(v.x), tf32r(v.y), tf32r(v.z), tf32r(v.w));
        }
        __syncthreads();

        #pragma unroll
        for (int ks = 0; ks < 4; ks++) {
            uint32_t af[2][4];
            #pragma unroll
            for (int mt = 0; mt < 2; mt++) {
                int rb = (wm * 32 + mt * 16) * 36 + ks * 8 + t;
                af[mt][0] = As[rb + g * 36];
                af[mt][1] = As[rb + (g + 8) * 36];
                af[mt][2] = As[rb + g * 36 + 4];
                af[mt][3] = As[rb + (g + 8) * 36 + 4];
            }
            #pragma unroll
            for (int nt = 0; nt < 4; nt++) {
                uint32_t b0 = Bs[(ks * 8 + t) * BSTR + wn * 32 + nt * 8 + g];
                uint32_t b1 = Bs[(ks * 8 + t + 4) * BSTR + wn * 32 + nt * 8 + g];
                mma8(acc[0][nt], af[0], b0, b1);
                mma8(acc[1][nt], af[1], b0, b1);
            }
        }
    }

    #pragma unroll
    for (int mt = 0; mt < 2; mt++) {
        int r0 = m0 + wm * 32 + mt * 16 + g;
        #pragma unroll
        for (int nt = 0; nt < 4; nt++) {
            int col = n0 + wn * 32 + nt * 8 + 2 * t;
            int hh = col >> 5, inner = col & 31;
            float bv0 = bias[col], bv1 = bias[col + 1];
            __half2 p0 = __floats2half2_rn((acc[mt][nt][0] + bv0) * osc,
                                           (acc[mt][nt][1] + bv1) * osc);
            __half2 p1 = __floats2half2_rn((acc[mt][nt][2] + bv0) * osc,
                                           (acc[mt][nt][3] + bv1) * osc);
            *reinterpret_cast<__half2*>(
                &out[((size_t)hh * N_TOK + r0) * HD + inner]) = p0;
            *reinterpret_cast<__half2*>(
                &out[((size_t)hh * N_TOK + r0 + 8) * HD + inner]) = p1;
        }
    }
}

// ---------------------------------------------------------------------------
// V projection, split-tf32 compute; epilogue writes fp16 V in row-pair layout.
// ---------------------------------------------------------------------------
__global__ __launch_bounds__(256) void projv_tc_kernel(
    const float* __restrict__ x, const float* __restrict__ W,
    const float* __restrict__ bias, __half* __restrict__ out)
{
    __shared__ uint32_t Ah[64 * 36], Al[64 * 36];
    __shared__ uint32_t Bh[32 * BSTR], Bl[32 * BSTR];

    const int tid = threadIdx.x;
    const int w = tid >> 5, lane = tid & 31;
    const int g = lane >> 2, t = lane & 3;
    const int wm = w & 1, wn = w >> 1;
    const int m0 = blockIdx.x * 64;
    const int n0 = blockIdx.y * 64;

    float acc[2][2][4] = {};

    for (int k0 = 0; k0 < 256; k0 += 32) {
        __syncthreads();
        #pragma unroll
        for (int i = 0; i < 2; i++) {
            int idx = tid + 256 * i;
            int row = idx >> 3;
            int col = (idx & 7) * 4;
            float4 v = *reinterpret_cast<const float4*>(
                &x[(size_t)(m0 + row) * IN_DIM + k0 + col]);
            uint4 h, l;
            split2(v.x, h.x, l.x); split2(v.y, h.y, l.y);
            split2(v.z, h.z, l.z); split2(v.w, h.w, l.w);
            *reinterpret_cast<uint4*>(&Ah[row * 36 + col]) = h;
            *reinterpret_cast<uint4*>(&Al[row * 36 + col]) = l;
        }
        #pragma unroll
        for (int i = 0; i < 2; i++) {
            int idx = tid + 256 * i;
            int kk = idx >> 4;
            int c = (idx & 15) * 4;
            int col = n0 + c;
            float4 v = *reinterpret_cast<const float4*>(
                &W[((size_t)(col >> 5) * 256 + k0 + kk) * HD + (col & 31)]);
            uint4 h, l;
            split2(v.x, h.x, l.x); split2(v.y, h.y, l.y);
            split2(v.z, h.z, l.z); split2(v.w, h.w, l.w);
            *reinterpret_cast<uint4*>(&Bh[kk * BSTR + c]) = h;
            *reinterpret_cast<uint4*>(&Bl[kk * BSTR + c]) = l;
        }
        __syncthreads();

        #pragma unroll
        for (int ks = 0; ks < 4; ks++) {
            uint32_t afh[2][4], afl[2][4];
            #pragma unroll
            for (int mt = 0; mt < 2; mt++) {
                int rb = (wm * 32 + mt * 16) * 36 + ks * 8 + t;
                afh[mt][0] = Ah[rb + g * 36];
                afh[mt][1] = Ah[rb + (g + 8) * 36];
                afh[mt][2] = Ah[rb + g * 36 + 4];
                afh[mt][3] = Ah[rb + (g + 8) * 36 + 4];
                afl[mt][0] = Al[rb + g * 36];
                afl[mt][1] = Al[rb + (g + 8) * 36];
                afl[mt][2] = Al[rb + g * 36 + 4];
                afl[mt][3] = Al[rb + (g + 8) * 36 + 4];
            }
            #pragma unroll
            for (int nt = 0; nt < 2; nt++) {
                int cb = wn * 16 + nt * 8 + g;
                uint32_t b0h = Bh[(ks * 8 + t) * BSTR + cb];
                uint32_t b1h = Bh[(ks * 8 + t + 4) * BSTR + cb];
                uint32_t b0l = Bl[(ks * 8 + t) * BSTR + cb];
                uint32_t b1l = Bl[(ks * 8 + t + 4) * BSTR + cb];
                #pragma unroll
                for (int mt = 0; mt < 2; mt++) {
                    mma8(acc[mt][nt], afh[mt], b0h, b1h);
                    mma8(acc[mt][nt], afh[mt], b0l, b1l);
                    mma8(acc[mt][nt], afl[mt], b0h, b1h);
                }
            }
        }
    }

    // epilogue: row-pair fp16 layout. r0 mod 16 == g.
    #pragma unroll
    for (int mt = 0; mt < 2; mt++) {
        int r0 = m0 + wm * 32 + mt * 16 + g;
        int jg2 = r0 >> 4;
        #pragma unroll
        for (int nt = 0; nt < 2; nt++) {
            int col = n0 + wn * 16 + nt * 8 + 2 * t;
            int hh = col >> 5, d0 = col & 31;
            float bv0 = bias[col], bv1 = bias[col + 1];
            __half* base = out + ((size_t)(hh * 256 + jg2) * 32) * 16;
            base[d0 * 16 + g]           = __float2half_rn(acc[mt][nt][0] + bv0);
            base[(d0 + 1) * 16 + g]     = __float2half_rn(acc[mt][nt][1] + bv1);
            base[d0 * 16 + g + 8]       = __float2half_rn(acc[mt][nt][2] + bv0);
            base[(d0 + 1) * 16 + g + 8] = __float2half_rn(acc[mt][nt][3] + bv1);
        }
    }
}

// ---------------------------------------------------------------------------
// Final linear, split-tf32: out = xcat @ lw^T + lb (known-good)
// ---------------------------------------------------------------------------
__global__ __launch_bounds__(256) void final_tc_kernel(
    const float* __restrict__ xcat, const float* __restrict__ lw,
    const float* __restrict__ lb, float* __restrict__ out)
{
    __shared__ uint32_t Ah[64 * 36], Al[64 * 36];
    __shared__ uint32_t Bh[32 * BSTR2], Bl[32 * BSTR2];

    const int tid = threadIdx.x;
    const int w = tid >> 5, lane = tid & 31;
    const int g = lane >> 2, t = lane & 3;
    const int wm = w & 1, wn = w >> 1;
    const int m0 = blockIdx.x * 64;
    const int n0 = blockIdx.y * 64;

    float acc[2][2][4] = {};

    for (int k0 = 0; k0 < 256; k0 += 32) {
        __syncthreads();
        #pragma unroll
        for (int i = 0; i < 2; i++) {
            int idx = tid + 256 * i;
            int row = idx >> 3;
            int col = (idx & 7) * 4;
            float4 v = *reinterpret_cast<const float4*>(
                &xcat[(size_t)(m0 + row) * HID + k0 + col]);
            uint4 h, l;
            split2(v.x, h.x, l.x); split2(v.y, h.y, l.y);
            split2(v.z, h.z, l.z); split2(v.w, h.w, l.w);
            *reinterpret_cast<uint4*>(&Ah[row * 36 + col]) = h;
            *reinterpret_cast<uint4*>(&Al[row * 36 + col]) = l;
        }
        #pragma unroll
        for (int i = 0; i < 2; i++) {
            int idx = tid + 256 * i;
            int c = idx >> 3;
            int kq = (idx & 7) * 4;
            float4 v = *reinterpret_cast<const float4*>(
                &lw[(size_t)(n0 + c) * HID + k0 + kq]);
            uint32_t h0, l0v, h1, l1v, h2, l2v, h3, l3v;
            split2(v.x, h0, l0v); split2(v.y, h1, l1v);
            split2(v.z, h2, l2v); split2(v.w, h3, l3v);
            Bh[(kq + 0) * BSTR2 + c] = h0;  Bl[(kq + 0) * BSTR2 + c] = l0v;
            Bh[(kq + 1) * BSTR2 + c] = h1;  Bl[(kq + 1) * BSTR2 + c] = l1v;
            Bh[(kq + 2) * BSTR2 + c] = h2;  Bl[(kq + 2) * BSTR2 + c] = l2v;
            Bh[(kq + 3) * BSTR2 + c] = h3;  Bl[(kq + 3) * BSTR2 + c] = l3v;
        }
        __syncthreads();

        #pragma unroll
        for (int ks = 0; ks < 4; ks++) {
            uint32_t afh[2][4], afl[2][4];
            #pragma unroll
            for (int mt = 0; mt < 2; mt++) {
                int rb = (wm * 32 + mt * 16) * 36 + ks * 8 + t;
                afh[mt][0] = Ah[rb + g * 36];
                afh[mt][1] = Ah[rb + (g + 8) * 36];
                afh[mt][2] = Ah[rb + g * 36 + 4];
                afh[mt][3] = Ah[rb + (g + 8) * 36 + 4];
                afl[mt][0] = Al[rb + g * 36];
                afl[mt][1] = Al[rb + (g + 8) * 36];
                afl[mt][2] = Al[rb + g * 36 + 4];
                afl[mt][3] = Al[rb + (g + 8) * 36 + 4];
            }
            #pragma unroll
            for (int nt = 0; nt < 2; nt++) {
                int cb = wn * 16 + nt * 8 + g;
                uint32_t b0h = Bh[(ks * 8 + t) * BSTR2 + cb];
                uint32_t b1h = Bh[(ks * 8 + t + 4) * BSTR2 + cb];
                uint32_t b0l = Bl[(ks * 8 + t) * BSTR2 + cb];
                uint32_t b1l = Bl[(ks * 8 + t + 4) * BSTR2 + cb];
                #pragma unroll
                for (int mt = 0; mt < 2; mt++) {
                    mma8(acc[mt][nt], afh[mt], b0h, b1h);
                    mma8(acc[mt][nt], afh[mt], b0l, b1l);
                    mma8(acc[mt][nt], afl[mt], b0h, b1h);
                }
            }
        }
    }

    #pragma unroll
    for (int mt = 0; mt < 2; mt++) {
        int r0 = m0 + wm * 32 + mt * 16 + g;
        #pragma unroll
        for (int nt = 0; nt < 2; nt++) {
            int col = n0 + wn * 16 + nt * 8 + 2 * t;
            float bv0 = lb[col], bv1 = lb[col + 1];
            *reinterpret_cast<float2*>(&out[(size_t)r0 * HID + col]) =
                make_float2(acc[mt][nt][0] + bv0, acc[mt][nt][1] + bv1);
            *reinterpret_cast<float2*>(&out[(size_t)(r0 + 8) * HID + col]) =
                make_float2(acc[mt][nt][2] + bv0, acc[mt][nt][3] + bv1);
        }
    }
}

// ---------------------------------------------------------------------------
// Flash attention, fp16 m16n8k16 (fp32 accumulate): half the MMA instructions
// of the tf32 version at the same per-instruction rate. cp.async double-
// buffered fp16 K/V tiles; P handoff is layout-natural (pack f16x2, no
// permutes). Grid (N/128, HEADS); block 256 (8 warps).
// ---------------------------------------------------------------------------
__global__ __launch_bounds__(256) void attn_mma_kernel(
    const __half* __restrict__ Qg, const __half* __restrict__ Kg,
    const __half* __restrict__ Vg, float* __restrict__ xcat)
{
    __shared__ __align__(16) char sbuf[SBUF_BYTES];
    const uint32_t sb = smem_u32(sbuf);

    const int tid = threadIdx.x;
    const int w = tid >> 5;
    const int lane = tid & 31;
    const int g = lane >> 2;
    const int t = lane & 3;
    const int h = blockIdx.y;
    const int q0 = blockIdx.x * QBLK;
    const int wm = w >> 1;
    const int m0 = wm * 32;
    const int c0 = (w & 1) * 32;      // KV col half

    const __half* Qh = Qg + (size_t)h * N_TOK * HD;
    const __half* Kh = Kg + (size_t)h * N_TOK * HD;
    const __half* Vh = Vg + (size_t)h * 256 * 512;   // row-pair layout base

    // ---- Q fragments (fp16 pairs, pre-scaled; direct word loads) ----
    // qf[mt][s] = {w0[8s+t], w1[8s+t], w0[8s+t+4], w1[8s+t+4]}
    uint32_t qf[2][2][4];
    #pragma unroll
    for (int mt = 0; mt < 2; mt++) {
        const uint32_t* q0p = reinterpret_cast<const uint32_t*>(
            Qh + (size_t)(q0 + m0 + mt * 16 + g) * HD);
        const uint32_t* q1p = q0p + 8 * HD / 2;
        #pragma unroll
        for (int s = 0; s < 2; s++) {
            qf[mt][s][0] = q0p[8 * s + t];
            qf[mt][s][1] = q1p[8 * s + t];
            qf[mt][s][2] = q0p[8 * s + t + 4];
            qf[mt][s][3] = q1p[8 * s + t + 4];
        }
    }

    float of[2][4][4] = {};
    float l[2][2] = {};

    // ---- fill geometry: 2 cp16 per thread per tile ----
    const int krow = tid >> 2;          // 0..63
    const int kch = tid & 3;            // 16B chunk within 64B K row
    const int vq = tid >> 6;            // V group 0..3
    const int vin = tid & 63;           // 16B chunk within 1KB group

    #define K_FILL(kb_, base_) \
        cp16((base_) + (krow * KW + kch * 4) * 4, \
             (const char*)(Kh + (size_t)((kb_) * KBLK + krow) * HD) + kch * 16)
    #define V_FILL(kb_, base_) \
        cp16((base_) + KBYTES + ((vq * 32 + (vin >> 1)) * VWS + (vin & 1) * 4) * 4, \
             (const char*)(Vh + ((size_t)((kb_) * 4 + vq)) * 512) + vin * 16)

    K_FILL(0, sb);
    V_FILL(0, sb);
    CP_COMMIT();

    for (int kb = 0; kb < NITER; kb++) {
        CP_WAIT0();
        __syncthreads();

        const int stage = kb & 1;
        if (kb + 1 < NITER) {
            const uint32_t nb = sb + (stage ^ 1) * STAGE_BYTES;
            K_FILL(kb + 1, nb);
            V_FILL(kb + 1, nb);
            CP_COMMIT();
        }

        const uint32_t* Ksp = reinterpret_cast<const uint32_t*>(sbuf + stage * STAGE_BYTES);
        const uint32_t* Vsp = reinterpret_cast<const uint32_t*>(sbuf + stage * STAGE_BYTES + KBYTES);

        #pragma unroll
        for (int jj = 0; jj < 2; jj++) {
            // ---- S for sub-tiles j = 2jj, 2jj+1 (each n8, k32) ----
            float sf[2][2][4] = {};   // [sj][mt]
            #pragma unroll
            for (int sj = 0; sj < 2; sj++) {
                const uint32_t* kr = &Ksp[(c0 + 8 * (2 * jj + sj) + g) * KW];
                uint32_t b00 = kr[t],     b01 = kr[t + 4];      // kstep 0
                uint32_t b10 = kr[8 + t], b11 = kr[8 + t + 4];  // kstep 1
                #pragma unroll
                for (int mt = 0; mt < 2; mt++) {
                    mma16h(sf[sj][mt], qf[mt][0], b00, b01);
                    mma16h(sf[sj][mt], qf[mt][1], b10, b11);
                }
            }

            // ---- exp + pack P to fp16 A-fragments (layout-natural) ----
            uint32_t pa[2][4];
            #pragma unroll
            for (int mt = 0; mt < 2; mt++) {
                float e00 = exp2f(sf[0][mt][0]);
                float e01 = exp2f(sf[0][mt][1]);
                float e02 = exp2f(sf[0][mt][2]);
                float e03 = exp2f(sf[0][mt][3]);
                float e10 = exp2f(sf[1][mt][0]);
                float e11 = exp2f(sf[1][mt][1]);
                float e12 = exp2f(sf[1][mt][2]);
                float e13 = exp2f(sf[1][mt][3]);
                l[mt][0] += (e00 + e01) + (e10 + e11);
                l[mt][1] += (e02 + e03) + (e12 + e13);
                pa[mt][0] = h2pack(e00, e01);   // (g,   k 2t:2t+1)
                pa[mt][1] = h2pack(e02, e03);   // (g+8, k 2t:2t+1)
                pa[mt][2] = h2pack(e10, e11);   // (g,   k 2t+8:2t+9)
                pa[mt][3] = h2pack(e12, e13);   // (g+8, k 2t+8:2t+9)
            }

            // ---- PV: O += P[32 x 16] @ V[16 x 32] ----
            const int q = 2 * (w & 1) + jj;
            #pragma unroll
            for (int nn = 0; nn < 4; nn++) {
                const uint32_t* vr = &Vsp[(q * 32 + g + 8 * nn) * VWS];
                uint32_t vb0 = vr[t], vb1 = vr[t + 4];
                mma16h(of[0][nn], pa[0], vb0, vb1);
                mma16h(of[1][nn], pa[1], vb0, vb1);
            }
        }
    }

    // ---- epilogue (sO/sL alias the KV buffers; safe after barrier) ----
    __syncthreads();
    float* sO = reinterpret_cast<float*>(sbuf);
    float* sL = reinterpret_cast<float*>(sbuf + QBLK * 34 * 4);

    #pragma unroll
    for (int mt = 0; mt < 2; mt++) {
        l[mt][0] += __shfl_xor_sync(0xffffffffu, l[mt][0], 1);
        l[mt][0] += __shfl_xor_sync(0xffffffffu, l[mt][0], 2);
        l[mt][1] += __shfl_xor_sync(0xffffffffu, l[mt][1], 1);
        l[mt][1] += __shfl_xor_sync(0xffffffffu, l[mt][1], 2);
    }

    if (w & 1) {
        #pragma unroll
        for (int mt = 0; mt < 2; mt++) {
            int r = m0 + mt * 16 + g;
            if (t == 0) { sL[r] = l[mt][0]; sL[r + 8] = l[mt][1]; }
            #pragma unroll
            for (int nn = 0; nn < 4; nn++) {
                *reinterpret_cast<float2*>(&sO[r * 34 + 8 * nn + 2 * t]) =
                    make_float2(of[mt][nn][0], of[mt][nn][1]);
                *reinterpret_cast<float2*>(&sO[(r + 8) * 34 + 8 * nn + 2 * t]) =
                    make_float2(of[mt][nn][2], of[mt][nn][3]);
            }
        }
    }
    __syncthreads();
    if (!(w & 1)) {
        #pragma unroll
        for (int mt = 0; mt < 2; mt++) {
            int r = m0 + mt * 16 + g;
            float L0 = l[mt][0] + sL[r];
            float L1 = l[mt][1] + sL[r + 8];
            float i0 = 1.0f / L0, i1 = 1.0f / L1;
            #pragma unroll
            for (int nn = 0; nn < 4; nn++) {
                float2 a = *reinterpret_cast<const float2*>(&sO[r * 34 + 8 * nn + 2 * t]);
                float2 b = *reinterpret_cast<const float2*>(&sO[(r + 8) * 34 + 8 * nn + 2 * t]);
                *reinterpret_cast<float2*>(
                    &xcat[(size_t)(q0 + r) * HID + h * HD + 8 * nn + 2 * t]) =
                    make_float2((of[mt][nn][0] + a.x) * i0, (of[mt][nn][1] + a.y) * i0);
                *reinterpret_cast<float2*>(
                    &xcat[(size_t)(q0 + r + 8) * HID + h * HD + 8 * nn + 2 * t]) =
                    make_float2((of[mt][nn][2] + b.x) * i1, (of[mt][nn][3] + b.y) * i1);
            }
        }
    }
}

// ---------------------------------------------------------------------------
extern "C" void kernel_launch(void* const* d_in, const int* in_sizes, int n_in,
                              void* d_out, int out_size)
{
    const float* x   = (const float*)d_in[0];
    const float* peQ = (const float*)d_in[1];
    const float* peK = (const float*)d_in[2];
    const float* WQ  = (const float*)d_in[4];
    const float* WK  = (const float*)d_in[5];
    const float* WV  = (const float*)d_in[6];
    const float* Qb  = (const float*)d_in[7];
    const float* Kb  = (const float*)d_in[8];
    const float* Vb  = (const float*)d_in[9];
    const float* lw  = (const float*)d_in[10];
    const float* lb  = (const float*)d_in[11];
    float* out = (float*)d_out;

    __half *qp, *kp, *vp;
    float *xc;
    cudaGetSymbolAddress((void**)&qp, g_Qh);
    cudaGetSymbolAddress((void**)&kp, g_Kh);
    cudaGetSymbolAddress((void**)&vp, g_Vh);
    cudaGetSymbolAddress((void**)&xc, g_xcat);

    projqk_kernel<<<dim3(N_TOK / 128, HID / 64, 2), 256>>>(
        x, peQ, peK, WQ, WK, Qb, Kb, qp, kp);
    projv_tc_kernel<<<dim3(N_TOK / 64, HID / 64), 256>>>(x, WV, Vb, vp);
    attn_mma_kernel<<<dim3(N_TOK / QBLK, HEADS), 256>>>(qp, kp, vp, xc);
    final_tc_kernel<<<dim3(N_TOK / 64, HID / 64), 256>>>(xc, lw, lb, out);
}

// round 17
// speedup vs baseline: 1.5151x; 1.0575x over previous
#include <cuda_runtime.h>
#include <cuda_fp16.h>
#include <math_constants.h>
#include <cstdint>

#define N_TOK 4096
#define IN_DIM 256
#define HID 256
#define HEADS 8
#define HD 32
#define QBLK 128
#define KBLK 64
#define NITER (N_TOK / KBLK)
#define KW 20      // K smem row stride (32b words); banks 20g+t conflict-free
#define VWS 12     // V smem (q,d)-row stride (words); banks 12g+t conflict-free
#define ASTRH 20   // projqk fp16 A-tile row stride (words)
#define BNSTR 72   // projqk fp16 B-tile kw-row stride (words)
#define BSTR 72    // projv B-tile row stride (conflict-free: 8t+g)
#define BSTR2 73   // final B-tile row stride

// attn SMEM: double-buffered [K | V] stages (fp16); epilogue aliases
#define KBYTES (64 * KW * 4)              // 5120
#define VBYTES (4 * 32 * VWS * 4)         // 6144
#define STAGE_BYTES (KBYTES + VBYTES)     // 11264
#define SBUF_BYTES (2 * STAGE_BYTES)      // 22528

// 1/sqrt(256) * log2(e): exp(x*0.0625) == exp2(x*SC2Q)
#define SC2Q (0.0625f * 1.4426950408889634f)

// Scratch (static __device__ arrays — allocation-free per harness rules)
// g_Qh: fp16, SC2Q-pre-scaled Q, row-major [h][n][d].
// g_Kh: fp16 K, row-major [h][n][d].
// g_Vh: fp16 V in row-pair layout: ((h*256+jg2)*32 + d)*16 + (r mod 16).
__device__ __half g_Qh[HEADS * N_TOK * HD];
__device__ __half g_Kh[HEADS * N_TOK * HD];
__device__ __half g_Vh[HEADS * N_TOK * HD];
__device__ float g_xcat[N_TOK * HID];

// ===========================================================================
__device__ __forceinline__ uint32_t tf32r(float x) {
    uint32_t u;
    asm("cvt.rna.tf32.f32 %0, %1;" : "=r"(u) : "f"(x));
    return u;
}
__device__ __forceinline__ void split2(float v, uint32_t& hi, uint32_t& lo) {
    hi = tf32r(v);
    lo = tf32r(v - __uint_as_float(hi));
}
__device__ __forceinline__ uint32_t smem_u32(const void* p) {
    uint32_t a;
    asm("{ .reg .u64 t; cvta.to.shared.u64 t, %1; cvt.u32.u64 %0, t; }" : "=r"(a) : "l"(p));
    return a;
}
__device__ __forceinline__ void cp16(uint32_t saddr, const void* gaddr) {
    asm volatile("cp.async.cg.shared.global [%0], [%1], 16;"
                 :: "r"(saddr), "l"(gaddr) : "memory");
}
#define CP_COMMIT() asm volatile("cp.async.commit_group;" ::: "memory")
#define CP_WAIT0()  asm volatile("cp.async.wait_group 0;" ::: "memory")

// pack (lo, hi) floats -> f16x2 (lo in low half)
__device__ __forceinline__ uint32_t h2pack(float lo, float hi) {
    uint32_t r;
    asm("cvt.rn.f16x2.f32 %0, %1, %2;" : "=r"(r) : "f"(hi), "f"(lo));
    return r;
}

// tf32 m16n8k8: D += A*B
__device__ __forceinline__ void mma8(float* d, const uint32_t* a,
                                     uint32_t b0, uint32_t b1) {
    asm volatile(
        "mma.sync.aligned.m16n8k8.row.col.f32.tf32.tf32.f32 "
        "{%0,%1,%2,%3}, {%4,%5,%6,%7}, {%8,%9}, {%0,%1,%2,%3};"
        : "+f"(d[0]), "+f"(d[1]), "+f"(d[2]), "+f"(d[3])
        : "r"(a[0]), "r"(a[1]), "r"(a[2]), "r"(a[3]), "r"(b0), "r"(b1));
}
// fp16 m16n8k16: D += A*B (fp32 accumulate) — 2x MAC/instr vs tf32 k8
__device__ __forceinline__ void mma16h(float* d, const uint32_t* a,
                                       uint32_t b0, uint32_t b1) {
    asm volatile(
        "mma.sync.aligned.m16n8k16.row.col.f32.f16.f16.f32 "
        "{%0,%1,%2,%3}, {%4,%5,%6,%7}, {%8,%9}, {%0,%1,%2,%3};"
        : "+f"(d[0]), "+f"(d[1]), "+f"(d[2]), "+f"(d[3])
        : "r"(a[0]), "r"(a[1]), "r"(a[2]), "r"(a[3]), "r"(b0), "r"(b1));
}

// ---------------------------------------------------------------------------
// Q/K projection via fp16 m16n8k16 mma.sync (fp32 accumulate): half the MMA
// instructions of the tf32 version; fp16 operands have the SAME 10-bit
// mantissa as tf32 so conversion error is statistically identical.
// Epilogue emits fp16 (Q pre-scaled by SC2Q). CTA 128x64, k-chunk 32.
// A tile: fp16 [row][k], stride ASTRH=20 words (banks 20g+t, conflict-free).
// B tile: k-pair words [kw][n], stride BNSTR=72 (banks 8t+g+8nt, c-free).
// Half order: even k in LOW half (matches proven attn K-path convention).
// ---------------------------------------------------------------------------
__global__ __launch_bounds__(256) void projqk_kernel(
    const float* __restrict__ x,
    const float* __restrict__ peQ, const float* __restrict__ peK,
    const float* __restrict__ WQ, const float* __restrict__ WK,
    const float* __restrict__ Qb, const float* __restrict__ Kb,
    __half* __restrict__ outQ, __half* __restrict__ outK)
{
    __shared__ uint32_t As[128 * ASTRH];   // 128 rows x 16 data words (+4 pad)
    __shared__ uint32_t Bs[16 * BNSTR];    // 16 k-pair rows x 64 n (+8 pad)

    const float* pe   = blockIdx.z ? peK : peQ;
    const float* W    = blockIdx.z ? WK  : WQ;
    const float* bias = blockIdx.z ? Kb  : Qb;
    __half* out       = blockIdx.z ? outK : outQ;
    const float osc   = blockIdx.z ? 1.0f : SC2Q;

    const int tid = threadIdx.x;
    const int w = tid >> 5, lane = tid & 31;
    const int g = lane >> 2, t = lane & 3;
    const int wm = w >> 1, wn = w & 1;
    const int m0 = blockIdx.x * 128;
    const int n0 = blockIdx.y * 64;

    float acc[2][4][4] = {};

    // B fill geometry: 256 items = 16 kw x 16 n-quads
    const int bkw = tid >> 4;            // k-pair 0..15
    const int bn4 = (tid & 15) * 4;      // n quad base

    for (int k0 = 0; k0 < 1024; k0 += 32) {
        __syncthreads();
        // ---- A tile: 128 rows x 32 k of concat(x,pe) -> fp16 pairs ----
        #pragma unroll
        for (int i = 0; i < 4; i++) {
            int idx = tid + 256 * i;
            int row = idx >> 3;
            int col = (idx & 7) * 4;     // k base (even)
            const float* src = (k0 < IN_DIM)
                ? &x[(size_t)(m0 + row) * IN_DIM + k0 + col]
                : &pe[(size_t)(m0 + row) * 768 + (k0 - IN_DIM) + col];
            float4 v = *reinterpret_cast<const float4*>(src);
            *reinterpret_cast<uint2*>(&As[row * ASTRH + (col >> 1)]) =
                make_uint2(h2pack(v.x, v.y), h2pack(v.z, v.w));
        }
        // ---- B tile: k-pair words [kw][n] from W (2 float4 loads/item) ----
        {
            int col = n0 + bn4;
            int hh = col >> 5, inner = col & 31;
            const float* wp = &W[((size_t)hh * 1024 + k0 + 2 * bkw) * HD + inner];
            float4 ve = *reinterpret_cast<const float4*>(wp);        // k even
            float4 vo = *reinterpret_cast<const float4*>(wp + HD);   // k odd
            *reinterpret_cast<uint4*>(&Bs[bkw * BNSTR + bn4]) =
                make_uint4(h2pack(ve.x, vo.x), h2pack(ve.y, vo.y),
                           h2pack(ve.z, vo.z), h2pack(ve.w, vo.w));
        }
        __syncthreads();

        #pragma unroll
        for (int ks = 0; ks < 2; ks++) {     // two k16 steps per chunk
            uint32_t af[2][4];
            #pragma unroll
            for (int mt = 0; mt < 2; mt++) {
                int rb = (wm * 32 + mt * 16) * ASTRH + ks * 8 + t;
                af[mt][0] = As[rb + g * ASTRH];          // (g,   k2t:2t+1)
                af[mt][1] = As[rb + (g + 8) * ASTRH];    // (g+8, k2t:2t+1)
                af[mt][2] = As[rb + g * ASTRH + 4];      // (g,   k2t+8:2t+9)
                af[mt][3] = As[rb + (g + 8) * ASTRH + 4];
            }
            #pragma unroll
            for (int nt = 0; nt < 4; nt++) {
                int cb = wn * 32 + nt * 8 + g;
                uint32_t b0 = Bs[(ks * 8 + t) * BNSTR + cb];
                uint32_t b1 = Bs[(ks * 8 + t + 4) * BNSTR + cb];
                mma16h(acc[0][nt], af[0], b0, b1);
                mma16h(acc[1][nt], af[1], b0, b1);
            }
        }
    }

    // ---- epilogue (identical C layout; emit fp16, Q pre-scaled) ----
    #pragma unroll
    for (int mt = 0; mt < 2; mt++) {
        int r0 = m0 + wm * 32 + mt * 16 + g;
        #pragma unroll
        for (int nt = 0; nt < 4; nt++) {
            int col = n0 + wn * 32 + nt * 8 + 2 * t;
            int hh = col >> 5, inner = col & 31;
            float bv0 = bias[col], bv1 = bias[col + 1];
            __half2 p0 = __floats2half2_rn((acc[mt][nt][0] + bv0) * osc,
                                           (acc[mt][nt][1] + bv1) * osc);
            __half2 p1 = __floats2half2_rn((acc[mt][nt][2] + bv0) * osc,
                                           (acc[mt][nt][3] + bv1) * osc);
            *reinterpret_cast<__half2*>(
                &out[((size_t)hh * N_TOK + r0) * HD + inner]) = p0;
            *reinterpret_cast<__half2*>(
                &out[((size_t)hh * N_TOK + r0 + 8) * HD + inner]) = p1;
        }
    }
}

// ---------------------------------------------------------------------------
// V projection, split-tf32 compute; epilogue writes fp16 V in row-pair layout.
// (known-good from round 16)
// ---------------------------------------------------------------------------
__global__ __launch_bounds__(256) void projv_tc_kernel(
    const float* __restrict__ x, const float* __restrict__ W,
    const float* __restrict__ bias, __half* __restrict__ out)
{
    __shared__ uint32_t Ah[64 * 36], Al[64 * 36];
    __shared__ uint32_t Bh[32 * BSTR], Bl[32 * BSTR];

    const int tid = threadIdx.x;
    const int w = tid >> 5, lane = tid & 31;
    const int g = lane >> 2, t = lane & 3;
    const int wm = w & 1, wn = w >> 1;
    const int m0 = blockIdx.x * 64;
    const int n0 = blockIdx.y * 64;

    float acc[2][2][4] = {};

    for (int k0 = 0; k0 < 256; k0 += 32) {
        __syncthreads();
        #pragma unroll
        for (int i = 0; i < 2; i++) {
            int idx = tid + 256 * i;
            int row = idx >> 3;
            int col = (idx & 7) * 4;
            float4 v = *reinterpret_cast<const float4*>(
                &x[(size_t)(m0 + row) * IN_DIM + k0 + col]);
            uint4 h, l;
            split2(v.x, h.x, l.x); split2(v.y, h.y, l.y);
            split2(v.z, h.z, l.z); split2(v.w, h.w, l.w);
            *reinterpret_cast<uint4*>(&Ah[row * 36 + col]) = h;
            *reinterpret_cast<uint4*>(&Al[row * 36 + col]) = l;
        }
        #pragma unroll
        for (int i = 0; i < 2; i++) {
            int idx = tid + 256 * i;
            int kk = idx >> 4;
            int c = (idx & 15) * 4;
            int col = n0 + c;
            float4 v = *reinterpret_cast<const float4*>(
                &W[((size_t)(col >> 5) * 256 + k0 + kk) * HD + (col & 31)]);
            uint4 h, l;
            split2(v.x, h.x, l.x); split2(v.y, h.y, l.y);
            split2(v.z, h.z, l.z); split2(v.w, h.w, l.w);
            *reinterpret_cast<uint4*>(&Bh[kk * BSTR + c]) = h;
            *reinterpret_cast<uint4*>(&Bl[kk * BSTR + c]) = l;
        }
        __syncthreads();

        #pragma unroll
        for (int ks = 0; ks < 4; ks++) {
            uint32_t afh[2][4], afl[2][4];
            #pragma unroll
            for (int mt = 0; mt < 2; mt++) {
                int rb = (wm * 32 + mt * 16) * 36 + ks * 8 + t;
                afh[mt][0] = Ah[rb + g * 36];
                afh[mt][1] = Ah[rb + (g + 8) * 36];
                afh[mt][2] = Ah[rb + g * 36 + 4];
                afh[mt][3] = Ah[rb + (g + 8) * 36 + 4];
                afl[mt][0] = Al[rb + g * 36];
                afl[mt][1] = Al[rb + (g + 8) * 36];
                afl[mt][2] = Al[rb + g * 36 + 4];
                afl[mt][3] = Al[rb + (g + 8) * 36 + 4];
            }
            #pragma unroll
            for (int nt = 0; nt < 2; nt++) {
                int cb = wn * 16 + nt * 8 + g;
                uint32_t b0h = Bh[(ks * 8 + t) * BSTR + cb];
                uint32_t b1h = Bh[(ks * 8 + t + 4) * BSTR + cb];
                uint32_t b0l = Bl[(ks * 8 + t) * BSTR + cb];
                uint32_t b1l = Bl[(ks * 8 + t + 4) * BSTR + cb];
                #pragma unroll
                for (int mt = 0; mt < 2; mt++) {
                    mma8(acc[mt][nt], afh[mt], b0h, b1h);
                    mma8(acc[mt][nt], afh[mt], b0l, b1l);
                    mma8(acc[mt][nt], afl[mt], b0h, b1h);
                }
            }
        }
    }

    // epilogue: row-pair fp16 layout. r0 mod 16 == g.
    #pragma unroll
    for (int mt = 0; mt < 2; mt++) {
        int r0 = m0 + wm * 32 + mt * 16 + g;
        int jg2 = r0 >> 4;
        #pragma unroll
        for (int nt = 0; nt < 2; nt++) {
            int col = n0 + wn * 16 + nt * 8 + 2 * t;
            int hh = col >> 5, d0 = col & 31;
            float bv0 = bias[col], bv1 = bias[col + 1];
            __half* base = out + ((size_t)(hh * 256 + jg2) * 32) * 16;
            base[d0 * 16 + g]           = __float2half_rn(acc[mt][nt][0] + bv0);
            base[(d0 + 1) * 16 + g]     = __float2half_rn(acc[mt][nt][1] + bv1);
            base[d0 * 16 + g + 8]       = __float2half_rn(acc[mt][nt][2] + bv0);
            base[(d0 + 1) * 16 + g + 8] = __float2half_rn(acc[mt][nt][3] + bv1);
        }
    }
}

// ---------------------------------------------------------------------------
// Final linear, split-tf32: out = xcat @ lw^T + lb (known-good)
// ---------------------------------------------------------------------------
__global__ __launch_bounds__(256) void final_tc_kernel(
    const float* __restrict__ xcat, const float* __restrict__ lw,
    const float* __restrict__ lb, float* __restrict__ out)
{
    __shared__ uint32_t Ah[64 * 36], Al[64 * 36];
    __shared__ uint32_t Bh[32 * BSTR2], Bl[32 * BSTR2];

    const int tid = threadIdx.x;
    const int w = tid >> 5, lane = tid & 31;
    const int g = lane >> 2, t = lane & 3;
    const int wm = w & 1, wn = w >> 1;
    const int m0 = blockIdx.x * 64;
    const int n0 = blockIdx.y * 64;

    float acc[2][2][4] = {};

    for (int k0 = 0; k0 < 256; k0 += 32) {
        __syncthreads();
        #pragma unroll
        for (int i = 0; i < 2; i++) {
            int idx = tid + 256 * i;
            int row = idx >> 3;
            int col = (idx & 7) * 4;
            float4 v = *reinterpret_cast<const float4*>(
                &xcat[(size_t)(m0 + row) * HID + k0 + col]);
            uint4 h, l;
            split2(v.x, h.x, l.x); split2(v.y, h.y, l.y);
            split2(v.z, h.z, l.z); split2(v.w, h.w, l.w);
            *reinterpret_cast<uint4*>(&Ah[row * 36 + col]) = h;
            *reinterpret_cast<uint4*>(&Al[row * 36 + col]) = l;
        }
        #pragma unroll
        for (int i = 0; i < 2; i++) {
            int idx = tid + 256 * i;
            int c = idx >> 3;
            int kq = (idx & 7) * 4;
            float4 v = *reinterpret_cast<const float4*>(
                &lw[(size_t)(n0 + c) * HID + k0 + kq]);
            uint32_t h0, l0v, h1, l1v, h2, l2v, h3, l3v;
            split2(v.x, h0, l0v); split2(v.y, h1, l1v);
            split2(v.z, h2, l2v); split2(v.w, h3, l3v);
            Bh[(kq + 0) * BSTR2 + c] = h0;  Bl[(kq + 0) * BSTR2 + c] = l0v;
            Bh[(kq + 1) * BSTR2 + c] = h1;  Bl[(kq + 1) * BSTR2 + c] = l1v;
            Bh[(kq + 2) * BSTR2 + c] = h2;  Bl[(kq + 2) * BSTR2 + c] = l2v;
            Bh[(kq + 3) * BSTR2 + c] = h3;  Bl[(kq + 3) * BSTR2 + c] = l3v;
        }
        __syncthreads();

        #pragma unroll
        for (int ks = 0; ks < 4; ks++) {
            uint32_t afh[2][4], afl[2][4];
            #pragma unroll
            for (int mt = 0; mt < 2; mt++) {
                int rb = (wm * 32 + mt * 16) * 36 + ks * 8 + t;
                afh[mt][0] = Ah[rb + g * 36];
                afh[mt][1] = Ah[rb + (g + 8) * 36];
                afh[mt][2] = Ah[rb + g * 36 + 4];
                afh[mt][3] = Ah[rb + (g + 8) * 36 + 4];
                afl[mt][0] = Al[rb + g * 36];
                afl[mt][1] = Al[rb + (g + 8) * 36];
                afl[mt][2] = Al[rb + g * 36 + 4];
                afl[mt][3] = Al[rb + (g + 8) * 36 + 4];
            }
            #pragma unroll
            for (int nt = 0; nt < 2; nt++) {
                int cb = wn * 16 + nt * 8 + g;
                uint32_t b0h = Bh[(ks * 8 + t) * BSTR2 + cb];
                uint32_t b1h = Bh[(ks * 8 + t + 4) * BSTR2 + cb];
                uint32_t b0l = Bl[(ks * 8 + t) * BSTR2 + cb];
                uint32_t b1l = Bl[(ks * 8 + t + 4) * BSTR2 + cb];
                #pragma unroll
                for (int mt = 0; mt < 2; mt++) {
                    mma8(acc[mt][nt], afh[mt], b0h, b1h);
                    mma8(acc[mt][nt], afh[mt], b0l, b1l);
                    mma8(acc[mt][nt], afl[mt], b0h, b1h);
                }
            }
        }
    }

    #pragma unroll
    for (int mt = 0; mt < 2; mt++) {
        int r0 = m0 + wm * 32 + mt * 16 + g;
        #pragma unroll
        for (int nt = 0; nt < 2; nt++) {
            int col = n0 + wn * 16 + nt * 8 + 2 * t;
            float bv0 = lb[col], bv1 = lb[col + 1];
            *reinterpret_cast<float2*>(&out[(size_t)r0 * HID + col]) =
                make_float2(acc[mt][nt][0] + bv0, acc[mt][nt][1] + bv1);
            *reinterpret_cast<float2*>(&out[(size_t)(r0 + 8) * HID + col]) =
                make_float2(acc[mt][nt][2] + bv0, acc[mt][nt][3] + bv1);
        }
    }
}

// ---------------------------------------------------------------------------
// Flash attention, fp16 m16n8k16 (known-good from round 16).
// ---------------------------------------------------------------------------
__global__ __launch_bounds__(256) void attn_mma_kernel(
    const __half* __restrict__ Qg, const __half* __restrict__ Kg,
    const __half* __restrict__ Vg, float* __restrict__ xcat)
{
    __shared__ __align__(16) char sbuf[SBUF_BYTES];
    const uint32_t sb = smem_u32(sbuf);

    const int tid = threadIdx.x;
    const int w = tid >> 5;
    const int lane = tid & 31;
    const int g = lane >> 2;
    const int t = lane & 3;
    const int h = blockIdx.y;
    const int q0 = blockIdx.x * QBLK;
    const int wm = w >> 1;
    const int m0 = wm * 32;
    const int c0 = (w & 1) * 32;      // KV col half

    const __half* Qh = Qg + (size_t)h * N_TOK * HD;
    const __half* Kh = Kg + (size_t)h * N_TOK * HD;
    const __half* Vh = Vg + (size_t)h * 256 * 512;   // row-pair layout base

    // ---- Q fragments (fp16 pairs, pre-scaled; direct word loads) ----
    uint32_t qf[2][2][4];
    #pragma unroll
    for (int mt = 0; mt < 2; mt++) {
        const uint32_t* q0p = reinterpret_cast<const uint32_t*>(
            Qh + (size_t)(q0 + m0 + mt * 16 + g) * HD);
        const uint32_t* q1p = q0p + 8 * HD / 2;
        #pragma unroll
        for (int s = 0; s < 2; s++) {
            qf[mt][s][0] = q0p[8 * s + t];
            qf[mt][s][1] = q1p[8 * s + t];
            qf[mt][s][2] = q0p[8 * s + t + 4];
            qf[mt][s][3] = q1p[8 * s + t + 4];
        }
    }

    float of[2][4][4] = {};
    float l[2][2] = {};

    // ---- fill geometry: 2 cp16 per thread per tile ----
    const int krow = tid >> 2;          // 0..63
    const int kch = tid & 3;            // 16B chunk within 64B K row
    const int vq = tid >> 6;            // V group 0..3
    const int vin = tid & 63;           // 16B chunk within 1KB group

    #define K_FILL(kb_, base_) \
        cp16((base_) + (krow * KW + kch * 4) * 4, \
             (const char*)(Kh + (size_t)((kb_) * KBLK + krow) * HD) + kch * 16)
    #define V_FILL(kb_, base_) \
        cp16((base_) + KBYTES + ((vq * 32 + (vin >> 1)) * VWS + (vin & 1) * 4) * 4, \
             (const char*)(Vh + ((size_t)((kb_) * 4 + vq)) * 512) + vin * 16)

    K_FILL(0, sb);
    V_FILL(0, sb);
    CP_COMMIT();

    for (int kb = 0; kb < NITER; kb++) {
        CP_WAIT0();
        __syncthreads();

        const int stage = kb & 1;
        if (kb + 1 < NITER) {
            const uint32_t nb = sb + (stage ^ 1) * STAGE_BYTES;
            K_FILL(kb + 1, nb);
            V_FILL(kb + 1, nb);
            CP_COMMIT();
        }

        const uint32_t* Ksp = reinterpret_cast<const uint32_t*>(sbuf + stage * STAGE_BYTES);
        const uint32_t* Vsp = reinterpret_cast<const uint32_t*>(sbuf + stage * STAGE_BYTES + KBYTES);

        #pragma unroll
        for (int jj = 0; jj < 2; jj++) {
            float sf[2][2][4] = {};   // [sj][mt]
            #pragma unroll
            for (int sj = 0; sj < 2; sj++) {
                const uint32_t* kr = &Ksp[(c0 + 8 * (2 * jj + sj) + g) * KW];
                uint32_t b00 = kr[t],     b01 = kr[t + 4];
                uint32_t b10 = kr[8 + t], b11 = kr[8 + t + 4];
                #pragma unroll
                for (int mt = 0; mt < 2; mt++) {
                    mma16h(sf[sj][mt], qf[mt][0], b00, b01);
                    mma16h(sf[sj][mt], qf[mt][1], b10, b11);
                }
            }

            uint32_t pa[2][4];
            #pragma unroll
            for (int mt = 0; mt < 2; mt++) {
                float e00 = exp2f(sf[0][mt][0]);
                float e01 = exp2f(sf[0][mt][1]);
                float e02 = exp2f(sf[0][mt][2]);
                float e03 = exp2f(sf[0][mt][3]);
                float e10 = exp2f(sf[1][mt][0]);
                float e11 = exp2f(sf[1][mt][1]);
                float e12 = exp2f(sf[1][mt][2]);
                float e13 = exp2f(sf[1][mt][3]);
                l[mt][0] += (e00 + e01) + (e10 + e11);
                l[mt][1] += (e02 + e03) + (e12 + e13);
                pa[mt][0] = h2pack(e00, e01);
                pa[mt][1] = h2pack(e02, e03);
                pa[mt][2] = h2pack(e10, e11);
                pa[mt][3] = h2pack(e12, e13);
            }

            const int q = 2 * (w & 1) + jj;
            #pragma unroll
            for (int nn = 0; nn < 4; nn++) {
                const uint32_t* vr = &Vsp[(q * 32 + g + 8 * nn) * VWS];
                uint32_t vb0 = vr[t], vb1 = vr[t + 4];
                mma16h(of[0][nn], pa[0], vb0, vb1);
                mma16h(of[1][nn], pa[1], vb0, vb1);
            }
        }
    }

    // ---- epilogue (sO/sL alias the KV buffers; safe after barrier) ----
    __syncthreads();
    float* sO = reinterpret_cast<float*>(sbuf);
    float* sL = reinterpret_cast<float*>(sbuf + QBLK * 34 * 4);

    #pragma unroll
    for (int mt = 0; mt < 2; mt++) {
        l[mt][0] += __shfl_xor_sync(0xffffffffu, l[mt][0], 1);
        l[mt][0] += __shfl_xor_sync(0xffffffffu, l[mt][0], 2);
        l[mt][1] += __shfl_xor_sync(0xffffffffu, l[mt][1], 1);
        l[mt][1] += __shfl_xor_sync(0xffffffffu, l[mt][1], 2);
    }

    if (w & 1) {
        #pragma unroll
        for (int mt = 0; mt < 2; mt++) {
            int r = m0 + mt * 16 + g;
            if (t == 0) { sL[r] = l[mt][0]; sL[r + 8] = l[mt][1]; }
            #pragma unroll
            for (int nn = 0; nn < 4; nn++) {
                *reinterpret_cast<float2*>(&sO[r * 34 + 8 * nn + 2 * t]) =
                    make_float2(of[mt][nn][0], of[mt][nn][1]);
                *reinterpret_cast<float2*>(&sO[(r + 8) * 34 + 8 * nn + 2 * t]) =
                    make_float2(of[mt][nn][2], of[mt][nn][3]);
            }
        }
    }
    __syncthreads();
    if (!(w & 1)) {
        #pragma unroll
        for (int mt = 0; mt < 2; mt++) {
            int r = m0 + mt * 16 + g;
            float L0 = l[mt][0] + sL[r];
            float L1 = l[mt][1] + sL[r + 8];
            float i0 = 1.0f / L0, i1 = 1.0f / L1;
            #pragma unroll
            for (int nn = 0; nn < 4; nn++) {
                float2 a = *reinterpret_cast<const float2*>(&sO[r * 34 + 8 * nn + 2 * t]);
                float2 b = *reinterpret_cast<const float2*>(&sO[(r + 8) * 34 + 8 * nn + 2 * t]);
                *reinterpret_cast<float2*>(
                    &xcat[(size_t)(q0 + r) * HID + h * HD + 8 * nn + 2 * t]) =
                    make_float2((of[mt][nn][0] + a.x) * i0, (of[mt][nn][1] + a.y) * i0);
                *reinterpret_cast<float2*>(
                    &xcat[(size_t)(q0 + r + 8) * HID + h * HD + 8 * nn + 2 * t]) =
                    make_float2((of[mt][nn][2] + b.x) * i1, (of[mt][nn][3] + b.y) * i1);
            }
        }
    }
}

// ---------------------------------------------------------------------------
extern "C" void kernel_launch(void* const* d_in, const int* in_sizes, int n_in,
                              void* d_out, int out_size)
{
    const float* x   = (const float*)d_in[0];
    const float* peQ = (const float*)d_in[1];
    const float* peK = (const float*)d_in[2];
    const float* WQ  = (const float*)d_in[4];
    const float* WK  = (const float*)d_in[5];
    const float* WV  = (const float*)d_in[6];
    const float* Qb  = (const float*)d_in[7];
    const float* Kb  = (const float*)d_in[8];
    const float* Vb  = (const float*)d_in[9];
    const float* lw  = (const float*)d_in[10];
    const float* lb  = (const float*)d_in[11];
    float* out = (float*)d_out;

    __half *qp, *kp, *vp;
    float *xc;
    cudaGetSymbolAddress((void**)&qp, g_Qh);
    cudaGetSymbolAddress((void**)&kp, g_Kh);
    cudaGetSymbolAddress((void**)&vp, g_Vh);
    cudaGetSymbolAddress((void**)&xc, g_xcat);

    projqk_kernel<<<dim3(N_TOK / 128, HID / 64, 2), 256>>>(
        x, peQ, peK, WQ, WK, Qb, Kb, qp, kp);
    projv_tc_kernel<<<dim3(N_TOK / 64, HID / 64), 256>>>(x, WV, Vb, vp);
    attn_mma_kernel<<<dim3(N_TOK / QBLK, HEADS), 256>>>(qp, kp, vp, xc);
    final_tc_kernel<<<dim3(N_TOK / 64, HID / 64), 256>>>(xc, lw, lb, out);
}